// round 12
// baseline (speedup 1.0000x reference)
#include <cuda_runtime.h>

#define B 8
#define T_IN 512
#define D 384
#define VPR (D / 4)            // 96 float4s per row
#define T_MEL 3584
#define MEL_MAX 2048
#define GTHREADS 192
#define GATHER_BLOCKS 2048     // 8 rows per block
#define GRID (GATHER_BLOCKS + B)

__device__ int g_idx[B * MEL_MAX];
__device__ volatile int g_flag[B];   // set by prep block b when g_idx[b] ready
__device__ int g_done;               // finish counter for state reset

__global__ void __launch_bounds__(GTHREADS) fused_kernel(const float* __restrict__ enc,
                                                         const int* __restrict__ dur,
                                                         const float* __restrict__ pitch,
                                                         float* __restrict__ enc_rep,
                                                         float* __restrict__ dec_lens_out,
                                                         float* __restrict__ pitch_avg_out) {
    const int tid = threadIdx.x;

    if (blockIdx.x < B) {
        // ================= prep block for batch b =================
        const int b = blockIdx.x;
        __shared__ int cum[T_IN + 1];
        __shared__ int wsum[4];

        if (tid < 128) {
            int4 dv = ((const int4*)(dur + b * T_IN))[tid];
            int s0 = dv.x, s1 = s0 + dv.y, s2 = s1 + dv.z, s3 = s2 + dv.w;
            int v = s3;
            const int wl = tid & 31;
            #pragma unroll
            for (int off = 1; off < 32; off <<= 1) {
                int n = __shfl_up_sync(0xffffffffu, v, off);
                if (wl >= off) v += n;
            }
            if (wl == 31) wsum[tid >> 5] = v;
            cum[4 * tid + 1] = v - s3 + s0;
            cum[4 * tid + 2] = v - s3 + s1;
            cum[4 * tid + 3] = v - s3 + s2;
            cum[4 * tid + 4] = v;
            if (tid == 0) cum[0] = 0;
        }
        __syncthreads();
        if (tid < 128) {
            const int wid = tid >> 5;
            int woff = 0;
            #pragma unroll
            for (int w = 0; w < 3; w++) if (w < wid) woff += wsum[w];
            if (woff) {
                cum[4 * tid + 1] += woff;
                cum[4 * tid + 2] += woff;
                cum[4 * tid + 3] += woff;
                cum[4 * tid + 4] += woff;
            }
        }
        __syncthreads();

        int total = cum[T_IN];
        const int totc = total < MEL_MAX ? total : MEL_MAX;
        int* idx = g_idx + b * MEL_MAX;

        // token fill covers [0, totc); tail fill covers [totc, MEL_MAX) — full coverage, no init pass
        #pragma unroll
        for (int k = 0; k < 3; k++) {
            const int t = tid + k * GTHREADS;
            if (t < T_IN) {
                const int start = cum[t];
                const int e = cum[t + 1] < MEL_MAX ? cum[t + 1] : MEL_MAX;
                #pragma unroll
                for (int j = 0; j < 7; j++) {
                    const int m = start + j;
                    if (m < e) idx[m] = t;
                }
            }
        }
        for (int m = totc + tid; m < MEL_MAX; m += GTHREADS) idx[m] = -1;

        // release: gather blocks for this batch may proceed
        __threadfence();
        __syncthreads();
        if (tid == 0) g_flag[b] = 1;

        // post-release work: dec_lens + pitch averages
        if (tid == 0) dec_lens_out[b] = (float)totc;
        const float* p = pitch + (size_t)b * T_MEL;
        #pragma unroll
        for (int k = 0; k < 3; k++) {
            const int t = tid + k * GTHREADS;
            if (t < T_IN) {
                const int start = cum[t];
                const int end = cum[t + 1];
                float s = 0.0f, cnt = 0.0f;
                #pragma unroll
                for (int j = 0; j < 7; j++) {
                    const int m = start + j;
                    if (m < end) {
                        float x = __ldg(&p[m]);
                        s += x;
                        if (x != 0.0f) cnt += 1.0f;
                    }
                }
                pitch_avg_out[b * T_IN + t] = (cnt != 0.0f) ? (s / cnt) : 0.0f;
            }
        }
    } else {
        // ================= gather block: 8 rows, 4 contiguous rows per thread =================
        const int gid = blockIdx.x - B;
        const int b = gid >> 8;                      // 256 blocks per batch
        const int lane = tid % VPR;
        const int rsub = tid / VPR;                  // 0..1
        const int row0 = gid * 8 + rsub * 4;         // 4 contiguous rows

        if (tid == 0) {
            while (g_flag[b] == 0) { }
            __threadfence();
        }
        __syncthreads();

        // phase 1: ONE int4 load -> 4 row indices
        const int4 t4 = *(const int4*)(g_idx + row0);

        // phase 2: 4 independent gathers
        const float4* encb = (const float4*)enc + (size_t)b * T_IN * VPR + lane;
        float4 v0 = (t4.x >= 0) ? __ldg(encb + (size_t)t4.x * VPR) : make_float4(0.f,0.f,0.f,0.f);
        float4 v1 = (t4.y >= 0) ? __ldg(encb + (size_t)t4.y * VPR) : make_float4(0.f,0.f,0.f,0.f);
        float4 v2 = (t4.z >= 0) ? __ldg(encb + (size_t)t4.z * VPR) : make_float4(0.f,0.f,0.f,0.f);
        float4 v3 = (t4.w >= 0) ? __ldg(encb + (size_t)t4.w * VPR) : make_float4(0.f,0.f,0.f,0.f);

        // phase 3: 4 coalesced independent stores
        float4* outp = (float4*)enc_rep + (size_t)row0 * VPR + lane;
        outp[0]           = v0;
        outp[VPR]         = v1;
        outp[2 * VPR]     = v2;
        outp[3 * VPR]     = v3;
    }

    // ---- reset shared state for next graph replay (last block to finish) ----
    if (threadIdx.x == 0) {
        int c = atomicAdd(&g_done, 1);
        if (c == GRID - 1) {
            g_done = 0;
            #pragma unroll
            for (int i = 0; i < B; i++) g_flag[i] = 0;
            __threadfence();
        }
    }
}

extern "C" void kernel_launch(void* const* d_in, const int* in_sizes, int n_in,
                              void* d_out, int out_size) {
    const float* enc_out = (const float*)d_in[0];   // [B, T_IN, D]
    const int* durations = (const int*)d_in[1];     // [B, T_IN]
    const float* pitch = (const float*)d_in[2];     // [B, 1, T_MEL]

    float* out = (float*)d_out;
    float* enc_rep = out;                               // B*MEL_MAX*D
    float* dec_lens = out + (size_t)B * MEL_MAX * D;    // B
    float* pitch_avg = dec_lens + B;                    // B*T_IN

    fused_kernel<<<GRID, GTHREADS>>>(enc_out, durations, pitch,
                                     enc_rep, dec_lens, pitch_avg);
}

// round 13
// speedup vs baseline: 1.1197x; 1.1197x over previous
#include <cuda_runtime.h>

#define B 8
#define T_IN 512
#define D 384
#define VPR (D / 4)            // 96 float4s per row
#define T_MEL 3584
#define MEL_MAX 2048
#define NT 192                 // threads per block
#define ROWS_PB 8              // rows per gather block
#define GATHER_BLOCKS (B * MEL_MAX / ROWS_PB)   // 2048
#define GRID (GATHER_BLOCKS + B)

__global__ void __launch_bounds__(NT) fused_kernel(const float* __restrict__ enc,
                                                   const int* __restrict__ dur,
                                                   const float* __restrict__ pitch,
                                                   float* __restrict__ enc_rep,
                                                   float* __restrict__ dec_lens_out,
                                                   float* __restrict__ pitch_avg_out) {
    const int tid = threadIdx.x;
    const bool is_gather = blockIdx.x < GATHER_BLOCKS;
    const int b = is_gather ? ((int)blockIdx.x >> 8)          // 256 gather blocks per batch
                            : ((int)blockIdx.x - GATHER_BLOCKS);

    __shared__ int cum[T_IN + 1];
    __shared__ int wsum[4];
    __shared__ int sidx[ROWS_PB];

    if (tid < ROWS_PB) sidx[tid] = -1;     // before first barrier; ordered by scan syncs

    // ---- in-block shuffle scan of this batch's 512 durations (threads 0..127) ----
    if (tid < 128) {
        int4 dv = ((const int4*)(dur + b * T_IN))[tid];
        int s0 = dv.x, s1 = s0 + dv.y, s2 = s1 + dv.z, s3 = s2 + dv.w;
        int v = s3;
        const int wl = tid & 31;
        #pragma unroll
        for (int off = 1; off < 32; off <<= 1) {
            int n = __shfl_up_sync(0xffffffffu, v, off);
            if (wl >= off) v += n;
        }
        if (wl == 31) wsum[tid >> 5] = v;
        cum[4 * tid + 1] = v - s3 + s0;
        cum[4 * tid + 2] = v - s3 + s1;
        cum[4 * tid + 3] = v - s3 + s2;
        cum[4 * tid + 4] = v;
        if (tid == 0) cum[0] = 0;
    }
    __syncthreads();
    if (tid < 128) {
        const int wid = tid >> 5;
        int woff = 0;
        #pragma unroll
        for (int w = 0; w < 3; w++) if (w < wid) woff += wsum[w];
        if (woff) {
            cum[4 * tid + 1] += woff;
            cum[4 * tid + 2] += woff;
            cum[4 * tid + 3] += woff;
            cum[4 * tid + 4] += woff;
        }
    }
    __syncthreads();

    if (is_gather) {
        const int r0 = (int)blockIdx.x * ROWS_PB;        // global first row (batches contiguous)
        const int r0b = r0 - b * MEL_MAX;                // row within batch

        // ---- scatter token ids intersecting [r0b, r0b+8) into smem ----
        #pragma unroll
        for (int k = 0; k < 3; k++) {
            const int t = tid + k * NT;
            if (t < T_IN) {
                const int start = cum[t];
                const int end = cum[t + 1];
                #pragma unroll
                for (int j = 0; j < 7; j++) {
                    const int m = start + j;
                    if (m < end && m >= r0b && m < r0b + ROWS_PB)
                        sidx[m - r0b] = t;
                }
            }
        }
        __syncthreads();

        // ---- gather: 4 contiguous rows per thread, idx from LDS ----
        const int lane = tid % VPR;
        const int rsub = tid / VPR;                      // 0..1
        const int lr = rsub * 4;                         // local row base
        const int t0 = sidx[lr + 0];
        const int t1 = sidx[lr + 1];
        const int t2 = sidx[lr + 2];
        const int t3 = sidx[lr + 3];

        const float4* encb = (const float4*)enc + (size_t)b * T_IN * VPR + lane;
        float4 v0 = (t0 >= 0) ? __ldg(encb + (size_t)t0 * VPR) : make_float4(0.f,0.f,0.f,0.f);
        float4 v1 = (t1 >= 0) ? __ldg(encb + (size_t)t1 * VPR) : make_float4(0.f,0.f,0.f,0.f);
        float4 v2 = (t2 >= 0) ? __ldg(encb + (size_t)t2 * VPR) : make_float4(0.f,0.f,0.f,0.f);
        float4 v3 = (t3 >= 0) ? __ldg(encb + (size_t)t3 * VPR) : make_float4(0.f,0.f,0.f,0.f);

        float4* outp = (float4*)enc_rep + ((size_t)r0 + lr) * VPR + lane;
        outp[0]       = v0;
        outp[VPR]     = v1;
        outp[2 * VPR] = v2;
        outp[3 * VPR] = v3;
    } else {
        // ---- pitch + dec_lens block for batch b ----
        if (tid == 0) {
            int total = cum[T_IN];
            dec_lens_out[b] = (float)(total < MEL_MAX ? total : MEL_MAX);
        }
        const float* p = pitch + (size_t)b * T_MEL;
        #pragma unroll
        for (int k = 0; k < 3; k++) {
            const int t = tid + k * NT;
            if (t < T_IN) {
                const int start = cum[t];
                const int end = cum[t + 1];
                float s = 0.0f, cnt = 0.0f;
                #pragma unroll
                for (int j = 0; j < 7; j++) {
                    const int m = start + j;
                    if (m < end) {
                        float x = __ldg(&p[m]);
                        s += x;
                        if (x != 0.0f) cnt += 1.0f;
                    }
                }
                pitch_avg_out[b * T_IN + t] = (cnt != 0.0f) ? (s / cnt) : 0.0f;
            }
        }
    }
}

extern "C" void kernel_launch(void* const* d_in, const int* in_sizes, int n_in,
                              void* d_out, int out_size) {
    const float* enc_out = (const float*)d_in[0];   // [B, T_IN, D]
    const int* durations = (const int*)d_in[1];     // [B, T_IN]
    const float* pitch = (const float*)d_in[2];     // [B, 1, T_MEL]

    float* out = (float*)d_out;
    float* enc_rep = out;                               // B*MEL_MAX*D
    float* dec_lens = out + (size_t)B * MEL_MAX * D;    // B
    float* pitch_avg = dec_lens + B;                    // B*T_IN

    fused_kernel<<<GRID, NT>>>(enc_out, durations, pitch,
                               enc_rep, dec_lens, pitch_avg);
}

// round 14
// speedup vs baseline: 1.2102x; 1.0809x over previous
#include <cuda_runtime.h>

#define B 8
#define T_IN 512
#define D 384
#define VPR (D / 4)            // 96 float4s per row
#define T_MEL 3584
#define MEL_MAX 2048
#define SLICES 8               // prep slices per batch
#define PREP_GRID (B * SLICES) // 64
#define PREP_NT 256
#define ROWS_SL (MEL_MAX / SLICES)   // 256 rows per prep slice
#define TOK_SL (T_IN / SLICES)       // 64 tokens per prep slice
#define GTHREADS 192
#define ROWS_PB 8
#define GATHER_GRID (B * MEL_MAX / ROWS_PB)  // 2048

// frame -> token map (-1 = zero row)
__device__ int g_idx[B * MEL_MAX];

// ---------------- prep: 64 blocks, each = (batch, slice) ----------------
__global__ void __launch_bounds__(PREP_NT) prep_kernel(const int* __restrict__ dur,
                                                       const float* __restrict__ pitch,
                                                       float* __restrict__ dec_lens_out,
                                                       float* __restrict__ pitch_avg_out) {
    const int b = blockIdx.x >> 3;
    const int s = blockIdx.x & 7;
    const int tid = threadIdx.x;

    __shared__ int cum[T_IN + 1];
    __shared__ int wsum[4];

    // cheap 2-barrier shuffle scan of this batch's durations (threads 0..127)
    if (tid < 128) {
        int4 dv = ((const int4*)(dur + b * T_IN))[tid];
        int s0 = dv.x, s1 = s0 + dv.y, s2 = s1 + dv.z, s3 = s2 + dv.w;
        int v = s3;
        const int wl = tid & 31;
        #pragma unroll
        for (int off = 1; off < 32; off <<= 1) {
            int n = __shfl_up_sync(0xffffffffu, v, off);
            if (wl >= off) v += n;
        }
        if (wl == 31) wsum[tid >> 5] = v;
        cum[4 * tid + 1] = v - s3 + s0;
        cum[4 * tid + 2] = v - s3 + s1;
        cum[4 * tid + 3] = v - s3 + s2;
        cum[4 * tid + 4] = v;
        if (tid == 0) cum[0] = 0;
    }
    __syncthreads();
    if (tid < 128) {
        const int wid = tid >> 5;
        int woff = 0;
        #pragma unroll
        for (int w = 0; w < 3; w++) if (w < wid) woff += wsum[w];
        if (woff) {
            cum[4 * tid + 1] += woff;
            cum[4 * tid + 2] += woff;
            cum[4 * tid + 3] += woff;
            cum[4 * tid + 4] += woff;
        }
    }
    __syncthreads();

    const int total = cum[T_IN];
    if (s == 0 && tid == 0)
        dec_lens_out[b] = (float)(total < MEL_MAX ? total : MEL_MAX);

    // g_idx for this slice: one row per thread, 9-step LDS binary search
    {
        const int m = s * ROWS_SL + tid;           // 256 rows, one per thread
        int t = -1;
        if (m < total) {
            int lo = 0, hi = T_IN;
            #pragma unroll
            for (int k = 0; k < 9; k++) {
                const int mid = (lo + hi) >> 1;
                if (cum[mid] <= m) lo = mid; else hi = mid;
            }
            t = lo;
        }
        g_idx[b * MEL_MAX + m] = t;
    }

    // pitch averages for this slice's 64 tokens (threads 0..63)
    if (tid < TOK_SL) {
        const int t = s * TOK_SL + tid;
        const int start = cum[t];
        const int end = cum[t + 1];
        const float* p = pitch + (size_t)b * T_MEL;
        float sm = 0.0f, cnt = 0.0f;
        #pragma unroll
        for (int j = 0; j < 7; j++) {
            const int m = start + j;
            if (m < end) {
                float x = __ldg(&p[m]);
                sm += x;
                if (x != 0.0f) cnt += 1.0f;
            }
        }
        pitch_avg_out[b * T_IN + t] = (cnt != 0.0f) ? (sm / cnt) : 0.0f;
    }
}

// ---------------- gather: 2048 x 192, 4 contiguous rows/thread, int4 idx ----------------
__global__ void __launch_bounds__(GTHREADS) gather_kernel(const float* __restrict__ enc,
                                                          float* __restrict__ out) {
    const int lane = threadIdx.x % VPR;
    const int rsub = threadIdx.x / VPR;              // 0..1
    const int row0 = blockIdx.x * ROWS_PB + rsub * 4;
    const int b = blockIdx.x >> 8;                   // 256 blocks per batch

    // phase 1: one int4 load -> 4 row indices (broadcast across the 96-lane group)
    const int4 t4 = *(const int4*)(g_idx + row0);

    // phase 2: 4 independent gathers
    const float4* encb = (const float4*)enc + (size_t)b * T_IN * VPR + lane;
    float4 v0 = (t4.x >= 0) ? __ldg(encb + (size_t)t4.x * VPR) : make_float4(0.f,0.f,0.f,0.f);
    float4 v1 = (t4.y >= 0) ? __ldg(encb + (size_t)t4.y * VPR) : make_float4(0.f,0.f,0.f,0.f);
    float4 v2 = (t4.z >= 0) ? __ldg(encb + (size_t)t4.z * VPR) : make_float4(0.f,0.f,0.f,0.f);
    float4 v3 = (t4.w >= 0) ? __ldg(encb + (size_t)t4.w * VPR) : make_float4(0.f,0.f,0.f,0.f);

    // phase 3: 4 coalesced independent stores
    float4* outp = (float4*)out + (size_t)row0 * VPR + lane;
    outp[0]       = v0;
    outp[VPR]     = v1;
    outp[2 * VPR] = v2;
    outp[3 * VPR] = v3;
}

extern "C" void kernel_launch(void* const* d_in, const int* in_sizes, int n_in,
                              void* d_out, int out_size) {
    const float* enc_out = (const float*)d_in[0];   // [B, T_IN, D]
    const int* durations = (const int*)d_in[1];     // [B, T_IN]
    const float* pitch = (const float*)d_in[2];     // [B, 1, T_MEL]

    float* out = (float*)d_out;
    float* enc_rep = out;                               // B*MEL_MAX*D
    float* dec_lens = out + (size_t)B * MEL_MAX * D;    // B
    float* pitch_avg = dec_lens + B;                    // B*T_IN

    prep_kernel<<<PREP_GRID, PREP_NT>>>(durations, pitch, dec_lens, pitch_avg);
    gather_kernel<<<GATHER_GRID, GTHREADS>>>(enc_out, enc_rep);
}

// round 15
// speedup vs baseline: 1.3090x; 1.0816x over previous
#include <cuda_runtime.h>

#define B 8
#define T_IN 512
#define D 384
#define VPR (D / 4)            // 96 float4s per row
#define T_MEL 3584
#define MEL_MAX 2048
#define GTHREADS 192
#define ROWS_PB 8
#define GATHER_BLOCKS (B * MEL_MAX / ROWS_PB)   // 2048
#define GRID2 (GATHER_BLOCKS + B)               // pitch blocks lead

// frame -> token map (-1 = zero row)
__device__ int g_idx[B * MEL_MAX];

// ---------------- shared scan helper (threads 0..127 scan 512 durations) ----------------
__device__ __forceinline__ void scan512(const int* __restrict__ dur, int b, int tid,
                                        int* cum, int* wsum) {
    if (tid < 128) {
        int4 dv = ((const int4*)(dur + b * T_IN))[tid];
        int s0 = dv.x, s1 = s0 + dv.y, s2 = s1 + dv.z, s3 = s2 + dv.w;
        int v = s3;
        const int wl = tid & 31;
        #pragma unroll
        for (int off = 1; off < 32; off <<= 1) {
            int n = __shfl_up_sync(0xffffffffu, v, off);
            if (wl >= off) v += n;
        }
        if (wl == 31) wsum[tid >> 5] = v;
        cum[4 * tid + 1] = v - s3 + s0;
        cum[4 * tid + 2] = v - s3 + s1;
        cum[4 * tid + 3] = v - s3 + s2;
        cum[4 * tid + 4] = v;
        if (tid == 0) cum[0] = 0;
    }
    __syncthreads();
    if (tid < 128) {
        const int wid = tid >> 5;
        int woff = 0;
        #pragma unroll
        for (int w = 0; w < 3; w++) if (w < wid) woff += wsum[w];
        if (woff) {
            cum[4 * tid + 1] += woff;
            cum[4 * tid + 2] += woff;
            cum[4 * tid + 3] += woff;
            cum[4 * tid + 4] += woff;
        }
    }
    __syncthreads();
}

// ---------------- k1: minimal idx writer (critical path only) ----------------
__global__ void __launch_bounds__(512) idx_kernel(const int* __restrict__ dur) {
    const int b = blockIdx.x;
    const int tid = threadIdx.x;
    __shared__ int cum[T_IN + 1];
    __shared__ int wsum[4];
    scan512(dur, b, tid, cum, wsum);

    int total = cum[T_IN];
    const int totc = total < MEL_MAX ? total : MEL_MAX;
    int* idx = g_idx + b * MEL_MAX;

    // token range fill covers [0, totc)
    const int start = cum[tid];
    const int e = cum[tid + 1] < MEL_MAX ? cum[tid + 1] : MEL_MAX;
    #pragma unroll
    for (int j = 0; j < 7; j++) {
        const int m = start + j;
        if (m < e) idx[m] = tid;
    }
    // tail fill [totc, MEL_MAX)
    for (int m = totc + tid; m < MEL_MAX; m += 512) idx[m] = -1;
}

// ---------------- k2: 8 pitch blocks (lead) + 2048 gather blocks ----------------
__global__ void __launch_bounds__(GTHREADS) main_kernel(const float* __restrict__ enc,
                                                        const int* __restrict__ dur,
                                                        const float* __restrict__ pitch,
                                                        float* __restrict__ enc_rep,
                                                        float* __restrict__ dec_lens_out,
                                                        float* __restrict__ pitch_avg_out) {
    const int tid = threadIdx.x;

    if (blockIdx.x < B) {
        // ---- pitch + dec_lens block for batch b (runs concurrent with gathers) ----
        const int b = blockIdx.x;
        __shared__ int cum[T_IN + 1];
        __shared__ int wsum[4];
        scan512(dur, b, tid, cum, wsum);

        if (tid == 0) {
            int total = cum[T_IN];
            dec_lens_out[b] = (float)(total < MEL_MAX ? total : MEL_MAX);
        }
        const float* p = pitch + (size_t)b * T_MEL;
        #pragma unroll
        for (int k = 0; k < 3; k++) {
            const int t = tid + k * GTHREADS;
            if (t < T_IN) {
                const int start = cum[t];
                const int end = cum[t + 1];
                float s = 0.0f, cnt = 0.0f;
                #pragma unroll
                for (int j = 0; j < 7; j++) {
                    const int m = start + j;
                    if (m < end) {
                        float x = __ldg(&p[m]);
                        s += x;
                        if (x != 0.0f) cnt += 1.0f;
                    }
                }
                pitch_avg_out[b * T_IN + t] = (cnt != 0.0f) ? (s / cnt) : 0.0f;
            }
        }
    } else {
        // ---- gather block: 8 rows, 4 contiguous rows per thread, int4 idx ----
        const int gid = blockIdx.x - B;
        const int lane = tid % VPR;
        const int rsub = tid / VPR;                  // 0..1
        const int row0 = gid * ROWS_PB + rsub * 4;
        const int b = gid >> 8;                      // 256 blocks per batch

        const int4 t4 = __ldg((const int4*)(g_idx + row0));

        const float4* encb = (const float4*)enc + (size_t)b * T_IN * VPR + lane;
        float4 v0 = (t4.x >= 0) ? __ldg(encb + (size_t)t4.x * VPR) : make_float4(0.f,0.f,0.f,0.f);
        float4 v1 = (t4.y >= 0) ? __ldg(encb + (size_t)t4.y * VPR) : make_float4(0.f,0.f,0.f,0.f);
        float4 v2 = (t4.z >= 0) ? __ldg(encb + (size_t)t4.z * VPR) : make_float4(0.f,0.f,0.f,0.f);
        float4 v3 = (t4.w >= 0) ? __ldg(encb + (size_t)t4.w * VPR) : make_float4(0.f,0.f,0.f,0.f);

        float4* outp = (float4*)enc_rep + (size_t)row0 * VPR + lane;
        outp[0]       = v0;
        outp[VPR]     = v1;
        outp[2 * VPR] = v2;
        outp[3 * VPR] = v3;
    }
}

extern "C" void kernel_launch(void* const* d_in, const int* in_sizes, int n_in,
                              void* d_out, int out_size) {
    const float* enc_out = (const float*)d_in[0];   // [B, T_IN, D]
    const int* durations = (const int*)d_in[1];     // [B, T_IN]
    const float* pitch = (const float*)d_in[2];     // [B, 1, T_MEL]

    float* out = (float*)d_out;
    float* enc_rep = out;                               // B*MEL_MAX*D
    float* dec_lens = out + (size_t)B * MEL_MAX * D;    // B
    float* pitch_avg = dec_lens + B;                    // B*T_IN

    idx_kernel<<<B, 512>>>(durations);
    main_kernel<<<GRID2, GTHREADS>>>(enc_out, durations, pitch,
                                     enc_rep, dec_lens, pitch_avg);
}

// round 16
// speedup vs baseline: 1.3606x; 1.0394x over previous
#include <cuda_runtime.h>

#define B 8
#define T_IN 512
#define D 384
#define VPR (D / 4)            // 96 float4s per row
#define T_MEL 3584
#define MEL_MAX 2048
#define NT 384                 // 4 row-groups x 96 lanes
#define SLICES 32              // per batch
#define ROWS_SL (MEL_MAX / SLICES)   // 64 rows per block
#define GRID (B * SLICES)      // 256 blocks — single wave
#define TOK_SL (T_IN / SLICES) // 16 pitch tokens per block

__global__ void __launch_bounds__(NT) fused_kernel(const float* __restrict__ enc,
                                                   const int* __restrict__ dur,
                                                   const float* __restrict__ pitch,
                                                   float* __restrict__ enc_rep,
                                                   float* __restrict__ dec_lens_out,
                                                   float* __restrict__ pitch_avg_out) {
    const int tid = threadIdx.x;
    const int b = blockIdx.x >> 5;
    const int s = blockIdx.x & 31;
    const int r0 = s * ROWS_SL;               // window [r0, r0+64) within batch

    __shared__ int cum[T_IN + 1];
    __shared__ int wsum[4];
    __shared__ int sidx[ROWS_SL];

    if (tid >= 128 && tid < 128 + ROWS_SL) sidx[tid - 128] = -1;  // init during scan phase

    // ---- 2-barrier shuffle scan of this batch's 512 durations (threads 0..127) ----
    if (tid < 128) {
        int4 dv = ((const int4*)(dur + b * T_IN))[tid];
        int s0 = dv.x, s1 = s0 + dv.y, s2 = s1 + dv.z, s3 = s2 + dv.w;
        int v = s3;
        const int wl = tid & 31;
        #pragma unroll
        for (int off = 1; off < 32; off <<= 1) {
            int n = __shfl_up_sync(0xffffffffu, v, off);
            if (wl >= off) v += n;
        }
        if (wl == 31) wsum[tid >> 5] = v;
        cum[4 * tid + 1] = v - s3 + s0;
        cum[4 * tid + 2] = v - s3 + s1;
        cum[4 * tid + 3] = v - s3 + s2;
        cum[4 * tid + 4] = v;
        if (tid == 0) cum[0] = 0;
    }
    __syncthreads();
    if (tid < 128) {
        const int wid = tid >> 5;
        int woff = 0;
        #pragma unroll
        for (int w = 0; w < 3; w++) if (w < wid) woff += wsum[w];
        if (woff) {
            cum[4 * tid + 1] += woff;
            cum[4 * tid + 2] += woff;
            cum[4 * tid + 3] += woff;
            cum[4 * tid + 4] += woff;
        }
    }
    __syncthreads();

    // ---- scatter token ids intersecting this 64-row window into smem ----
    #pragma unroll
    for (int k = 0; k < 2; k++) {
        const int t = tid + k * NT;
        if (t < T_IN) {
            const int start = cum[t];
            const int end = cum[t + 1];
            const int e = end < MEL_MAX ? end : MEL_MAX;
            #pragma unroll
            for (int j = 0; j < 7; j++) {
                const int m = start + j;
                if (m < e && m >= r0 && m < r0 + ROWS_SL)
                    sidx[m - r0] = t;
            }
        }
    }
    __syncthreads();

    // ---- copy 64 rows: 4 row-groups x 16 rows/thread, 2 chunks of 8 chains ----
    const int lane = tid % VPR;
    const int rsub = tid / VPR;               // 0..3
    const float4* encb = (const float4*)enc + (size_t)b * T_IN * VPR + lane;
    float4* outb = (float4*)enc_rep + ((size_t)b * MEL_MAX + r0) * VPR + lane;

    #pragma unroll
    for (int chunk = 0; chunk < 2; chunk++) {
        int t[8];
        #pragma unroll
        for (int i = 0; i < 8; i++)
            t[i] = sidx[rsub + 4 * (chunk * 8 + i)];
        float4 v[8];
        #pragma unroll
        for (int i = 0; i < 8; i++)
            v[i] = (t[i] >= 0) ? __ldg(encb + (size_t)t[i] * VPR)
                               : make_float4(0.f, 0.f, 0.f, 0.f);
        #pragma unroll
        for (int i = 0; i < 8; i++)
            outb[(size_t)(rsub + 4 * (chunk * 8 + i)) * VPR] = v[i];
    }

    // ---- pitch averages: last 16 threads handle this block's 16 tokens ----
    if (tid >= NT - TOK_SL) {
        const int t = s * TOK_SL + (tid - (NT - TOK_SL));
        const int start = cum[t];
        const int end = cum[t + 1];
        const float* p = pitch + (size_t)b * T_MEL;
        float sm = 0.0f, cnt = 0.0f;
        #pragma unroll
        for (int j = 0; j < 7; j++) {
            const int m = start + j;
            if (m < end) {
                float x = __ldg(&p[m]);
                sm += x;
                if (x != 0.0f) cnt += 1.0f;
            }
        }
        pitch_avg_out[b * T_IN + t] = (cnt != 0.0f) ? (sm / cnt) : 0.0f;
    }

    if (tid == 0 && s == 0) {
        int total = cum[T_IN];
        dec_lens_out[b] = (float)(total < MEL_MAX ? total : MEL_MAX);
    }
}

extern "C" void kernel_launch(void* const* d_in, const int* in_sizes, int n_in,
                              void* d_out, int out_size) {
    const float* enc_out = (const float*)d_in[0];   // [B, T_IN, D]
    const int* durations = (const int*)d_in[1];     // [B, T_IN]
    const float* pitch = (const float*)d_in[2];     // [B, 1, T_MEL]

    float* out = (float*)d_out;
    float* enc_rep = out;                               // B*MEL_MAX*D
    float* dec_lens = out + (size_t)B * MEL_MAX * D;    // B
    float* pitch_avg = dec_lens + B;                    // B*T_IN

    fused_kernel<<<GRID, NT>>>(enc_out, durations, pitch,
                               enc_rep, dec_lens, pitch_avg);
}

// round 17
// speedup vs baseline: 1.3901x; 1.0217x over previous
#include <cuda_runtime.h>

#define B 8
#define T_IN 512
#define D 384
#define VPR (D / 4)            // 96 float4s per row
#define T_MEL 3584
#define MEL_MAX 2048
#define NT 384                 // 4 row-groups x 96 lanes
#define SLICES 64              // per batch
#define ROWS_SL (MEL_MAX / SLICES)   // 32 rows per block
#define GRID (B * SLICES)      // 512 blocks
#define TOK_SL (T_IN / SLICES) // 8 pitch tokens per block

__global__ void __launch_bounds__(NT) fused_kernel(const float* __restrict__ enc,
                                                   const int* __restrict__ dur,
                                                   const float* __restrict__ pitch,
                                                   float* __restrict__ enc_rep,
                                                   float* __restrict__ dec_lens_out,
                                                   float* __restrict__ pitch_avg_out) {
    const int tid = threadIdx.x;
    const int b = blockIdx.x >> 6;
    const int s = blockIdx.x & 63;
    const int r0 = s * ROWS_SL;               // window [r0, r0+32) within batch

    __shared__ int cum[T_IN + 1];
    __shared__ int wsum[4];
    __shared__ int sidx[ROWS_SL];

    if (tid >= 128 && tid < 128 + ROWS_SL) sidx[tid - 128] = -1;  // init during scan phase

    // ---- 2-barrier shuffle scan of this batch's 512 durations (threads 0..127) ----
    if (tid < 128) {
        int4 dv = ((const int4*)(dur + b * T_IN))[tid];
        int s0 = dv.x, s1 = s0 + dv.y, s2 = s1 + dv.z, s3 = s2 + dv.w;
        int v = s3;
        const int wl = tid & 31;
        #pragma unroll
        for (int off = 1; off < 32; off <<= 1) {
            int n = __shfl_up_sync(0xffffffffu, v, off);
            if (wl >= off) v += n;
        }
        if (wl == 31) wsum[tid >> 5] = v;
        cum[4 * tid + 1] = v - s3 + s0;
        cum[4 * tid + 2] = v - s3 + s1;
        cum[4 * tid + 3] = v - s3 + s2;
        cum[4 * tid + 4] = v;
        if (tid == 0) cum[0] = 0;
    }
    __syncthreads();
    if (tid < 128) {
        const int wid = tid >> 5;
        int woff = 0;
        #pragma unroll
        for (int w = 0; w < 3; w++) if (w < wid) woff += wsum[w];
        if (woff) {
            cum[4 * tid + 1] += woff;
            cum[4 * tid + 2] += woff;
            cum[4 * tid + 3] += woff;
            cum[4 * tid + 4] += woff;
        }
    }
    __syncthreads();

    // ---- scatter token ids intersecting this 32-row window into smem ----
    #pragma unroll
    for (int k = 0; k < 2; k++) {
        const int t = tid + k * NT;
        if (t < T_IN) {
            const int start = cum[t];
            const int end = cum[t + 1];
            const int e = end < MEL_MAX ? end : MEL_MAX;
            #pragma unroll
            for (int j = 0; j < 7; j++) {
                const int m = start + j;
                if (m < e && m >= r0 && m < r0 + ROWS_SL)
                    sidx[m - r0] = t;
            }
        }
    }
    __syncthreads();

    // ---- copy 32 rows: 4 row-groups x 8 rows/thread, 8 independent chains ----
    const int lane = tid % VPR;
    const int rsub = tid / VPR;               // 0..3
    const float4* encb = (const float4*)enc + (size_t)b * T_IN * VPR + lane;
    float4* outb = (float4*)enc_rep + ((size_t)b * MEL_MAX + r0) * VPR + lane;

    int t[8];
    #pragma unroll
    for (int i = 0; i < 8; i++)
        t[i] = sidx[rsub + 4 * i];
    float4 v[8];
    #pragma unroll
    for (int i = 0; i < 8; i++)
        v[i] = (t[i] >= 0) ? __ldg(encb + (size_t)t[i] * VPR)
                           : make_float4(0.f, 0.f, 0.f, 0.f);
    #pragma unroll
    for (int i = 0; i < 8; i++)
        outb[(size_t)(rsub + 4 * i) * VPR] = v[i];

    // ---- pitch averages: last 8 threads handle this block's 8 tokens ----
    if (tid >= NT - TOK_SL) {
        const int t2 = s * TOK_SL + (tid - (NT - TOK_SL));
        const int start = cum[t2];
        const int end = cum[t2 + 1];
        const float* p = pitch + (size_t)b * T_MEL;
        float sm = 0.0f, cnt = 0.0f;
        #pragma unroll
        for (int j = 0; j < 7; j++) {
            const int m = start + j;
            if (m < end) {
                float x = __ldg(&p[m]);
                sm += x;
                if (x != 0.0f) cnt += 1.0f;
            }
        }
        pitch_avg_out[b * T_IN + t2] = (cnt != 0.0f) ? (sm / cnt) : 0.0f;
    }

    if (tid == 0 && s == 0) {
        int total = cum[T_IN];
        dec_lens_out[b] = (float)(total < MEL_MAX ? total : MEL_MAX);
    }
}

extern "C" void kernel_launch(void* const* d_in, const int* in_sizes, int n_in,
                              void* d_out, int out_size) {
    const float* enc_out = (const float*)d_in[0];   // [B, T_IN, D]
    const int* durations = (const int*)d_in[1];     // [B, T_IN]
    const float* pitch = (const float*)d_in[2];     // [B, 1, T_MEL]

    float* out = (float*)d_out;
    float* enc_rep = out;                               // B*MEL_MAX*D
    float* dec_lens = out + (size_t)B * MEL_MAX * D;    // B
    float* pitch_avg = dec_lens + B;                    // B*T_IN

    fused_kernel<<<GRID, NT>>>(enc_out, durations, pitch,
                               enc_rep, dec_lens, pitch_avg);
}